// round 6
// baseline (speedup 1.0000x reference)
#include <cuda_runtime.h>
#include <cstdint>

// Problem constants (fixed by the reference: SHAPE = (8192, 4096), P = 0.3)
#define N_ELEMS   (8192 * 4096)        // 33,554,432 floats
#define N_WORDS   (N_ELEMS / 32)       // 1,048,576 uint32 mask words = 4 MB
#define N_FLOAT4  (N_ELEMS / 4)        // 8,388,608 float4s

// How much of X to prefetch into L2 during the scatter phase.
// 96 MB (of 128 MB) + 4 MB mask fits comfortably in ~126 MB L2.
#define PF_BYTES  (96 * 1024 * 1024)
#define PF_LINES  (PF_BYTES / 128)     // 786,432 cache lines

// Scratch: 1 bit per element. Zero at module load; every apply pass
// re-zeroes it for the next graph replay (self-cleaning).
__device__ uint32_t g_mask[N_WORDS];

// ---------------------------------------------------------------------------
// Kernel 1: scatter-set bits + L2 prefetch of X.
// Flat maximal-width launch: each thread does one int4 idx load + 4 RED.ORs.
// Threads i < PF_LINES additionally prefetch one 128B line of X into L2 —
// DRAM is ~90% idle during the scatter, so this hides most of the apply
// kernel's X-read traffic behind the (LSU-issue-bound) scatter.
// ---------------------------------------------------------------------------
__global__ void set_bits_kernel(const int4* __restrict__ idx4, int n_quads,
                                const int* __restrict__ idx, int k,
                                const char* __restrict__ Xbytes) {
    int i = blockIdx.x * blockDim.x + threadIdx.x;

    // prefetch first (fire-and-forget, data arrives while REDs drain)
    if (i < PF_LINES) {
        const char* p = Xbytes + (size_t)i * 128;
        asm volatile("prefetch.global.L2 [%0];" :: "l"(p));
    }

    if (i < n_quads) {
        int4 v = __ldcs(&idx4[i]);
        unsigned int a = (unsigned int)v.x;
        unsigned int b = (unsigned int)v.y;
        unsigned int c = (unsigned int)v.z;
        unsigned int d = (unsigned int)v.w;
        atomicOr(&g_mask[a >> 5], 1u << (a & 31));
        atomicOr(&g_mask[b >> 5], 1u << (b & 31));
        atomicOr(&g_mask[c >> 5], 1u << (c & 31));
        atomicOr(&g_mask[d >> 5], 1u << (d & 31));
    }
    // tail (k % 4 != 0)
    if (i == 0) {
        for (int j = n_quads * 4; j < k; j++) {
            unsigned int a = (unsigned int)idx[j];
            atomicOr(&g_mask[a >> 5], 1u << (a & 31));
        }
    }
}

// ---------------------------------------------------------------------------
// Kernel 2: fused copy + masked zero + mask self-clean, ILP=8.
// Each thread owns 8 CONSECUTIVE float4s (128 B) = exactly ONE mask word,
// which it alone reads and alone cleans -> the clean store is ordered after
// the thread's own loads by warp program order. Race-free by construction.
// Mask word loads are perfectly coalesced (32 consecutive words per warp).
// X read .cs (hit prefetched L2 lines, then evict-first), out written .cs.
// ---------------------------------------------------------------------------
__global__ void __launch_bounds__(256)
apply_mask_kernel(const float4* __restrict__ X, float4* __restrict__ out) {
    int t = blockIdx.x * blockDim.x + threadIdx.x;   // 0 .. N_WORDS-1
    int f = t * 8;                                   // first float4 index

    uint32_t w = g_mask[t];

    float4 v[8];
#pragma unroll
    for (int j = 0; j < 8; j++) v[j] = __ldcs(&X[f + j]);

#pragma unroll
    for (int j = 0; j < 8; j++) {
        uint32_t nib = w >> (j * 4);
        if (nib & 1u) v[j].x = 0.0f;
        if (nib & 2u) v[j].y = 0.0f;
        if (nib & 4u) v[j].z = 0.0f;
        if (nib & 8u) v[j].w = 0.0f;
        __stcs(&out[f + j], v[j]);
    }

    g_mask[t] = 0u;   // self-clean own word for next graph replay
}

extern "C" void kernel_launch(void* const* d_in, const int* in_sizes, int n_in,
                              void* d_out, int out_size) {
    const float* X = (const float*)d_in[0];
    const int* drop_idx = (const int*)d_in[1];   // JAX x64-disabled => int32
    int k = in_sizes[1];                          // number of indices
    float* out = (float*)d_out;

    // 1) scatter bits + L2 prefetch of X (mask is zero: init or prior apply)
    {
        int n_quads = k / 4;
        int threads = 256;
        int work = (n_quads > PF_LINES) ? n_quads : PF_LINES;
        int blocks = (work + threads - 1) / threads;
        set_bits_kernel<<<blocks, threads>>>((const int4*)drop_idx, n_quads,
                                             drop_idx, k, (const char*)X);
    }

    // 2) fused copy + zero + mask clear (one mask word / 128 B per thread)
    {
        int blocks = N_WORDS / 256;    // 4096
        apply_mask_kernel<<<blocks, 256>>>((const float4*)X, (float4*)out);
    }
}

// round 8
// speedup vs baseline: 1.4090x; 1.4090x over previous
#include <cuda_runtime.h>
#include <cstdint>

// Problem constants (fixed by the reference: SHAPE = (8192, 4096), P = 0.3)
#define N_ELEMS   (8192 * 4096)        // 33,554,432 floats
#define N_WORDS   (N_ELEMS / 32)       // 1,048,576 uint32 mask words = 4 MB
#define N_FLOAT4  (N_ELEMS / 4)        // 8,388,608 float4s

// How much of X to prefetch into L2 during the scatter phase.
#define PF_BYTES  (96 * 1024 * 1024)
#define PF_LINES  (PF_BYTES / 128)     // 786,432 cache lines

// Scratch: 1 bit per element. Zero at module load; every apply pass
// re-zeroes it for the next graph replay (self-cleaning).
__device__ uint32_t g_mask[N_WORDS];

// ---------------------------------------------------------------------------
// Kernel 1: scatter-set bits + L2 prefetch of X.
// Flat maximal-width launch (best measured scatter config): each thread does
// one int4 idx load + 4 RED.ORs and exits. Threads i < PF_LINES additionally
// prefetch one 128B line of X into L2 — DRAM is ~90% idle during the
// LSU-issue-bound scatter, so the apply kernel's X reads become L2 hits.
// ---------------------------------------------------------------------------
__global__ void set_bits_kernel(const int4* __restrict__ idx4, int n_quads,
                                const int* __restrict__ idx, int k,
                                const char* __restrict__ Xbytes) {
    int i = blockIdx.x * blockDim.x + threadIdx.x;

    if (i < PF_LINES) {
        const char* p = Xbytes + (size_t)i * 128;
        asm volatile("prefetch.global.L2 [%0];" :: "l"(p));
    }

    if (i < n_quads) {
        int4 v = __ldcs(&idx4[i]);
        unsigned int a = (unsigned int)v.x;
        unsigned int b = (unsigned int)v.y;
        unsigned int c = (unsigned int)v.z;
        unsigned int d = (unsigned int)v.w;
        atomicOr(&g_mask[a >> 5], 1u << (a & 31));
        atomicOr(&g_mask[b >> 5], 1u << (b & 31));
        atomicOr(&g_mask[c >> 5], 1u << (c & 31));
        atomicOr(&g_mask[d >> 5], 1u << (d & 31));
    }
    // tail (k % 4 != 0)
    if (i == 0) {
        for (int j = n_quads * 4; j < k; j++) {
            unsigned int a = (unsigned int)idx[j];
            atomicOr(&g_mask[a >> 5], 1u << (a & 31));
        }
    }
}

// ---------------------------------------------------------------------------
// Kernel 2: fused copy + masked zero + mask self-clean.
// COALESCED: consecutive threads handle consecutive float4s (each LDG.128 =
// 4 wavefronts, not 32). ILP=2 via block-strided second element. 8 adjacent
// same-warp threads share one mask word; the (tid&7)==0 lane cleans both of
// its group's words AFTER the loads — readers and cleaner are in the same
// warp, so warp program order makes the self-clean race-free.
// X read .cs (hits prefetched L2 lines), out written .cs (evict-first).
// ---------------------------------------------------------------------------
__global__ void __launch_bounds__(512)
apply_mask_kernel(const float4* __restrict__ X, float4* __restrict__ out) {
    int tid = threadIdx.x;
    int i0 = blockIdx.x * 1024 + tid;      // first float4
    int i1 = i0 + 512;                     // second float4 (block-strided)

    uint32_t w0 = g_mask[i0 >> 3];
    uint32_t w1 = g_mask[i1 >> 3];
    float4 v0 = __ldcs(&X[i0]);
    float4 v1 = __ldcs(&X[i1]);

    uint32_t n0 = w0 >> ((i0 & 7) * 4);
    if (n0 & 1u) v0.x = 0.0f;
    if (n0 & 2u) v0.y = 0.0f;
    if (n0 & 4u) v0.z = 0.0f;
    if (n0 & 8u) v0.w = 0.0f;
    __stcs(&out[i0], v0);

    uint32_t n1 = w1 >> ((i1 & 7) * 4);
    if (n1 & 1u) v1.x = 0.0f;
    if (n1 & 2u) v1.y = 0.0f;
    if (n1 & 4u) v1.z = 0.0f;
    if (n1 & 8u) v1.w = 0.0f;
    __stcs(&out[i1], v1);

    // self-clean for next graph replay (one lane per 8-thread group cleans
    // that group's two mask words; same warp as all readers of those words)
    if ((tid & 7) == 0) {
        g_mask[i0 >> 3] = 0u;
        g_mask[i1 >> 3] = 0u;
    }
}

extern "C" void kernel_launch(void* const* d_in, const int* in_sizes, int n_in,
                              void* d_out, int out_size) {
    const float* X = (const float*)d_in[0];
    const int* drop_idx = (const int*)d_in[1];   // JAX x64-disabled => int32
    int k = in_sizes[1];                          // number of indices
    float* out = (float*)d_out;

    // 1) scatter bits + L2 prefetch of X (mask is zero: init or prior apply)
    {
        int n_quads = k / 4;
        int threads = 256;
        int work = (n_quads > PF_LINES) ? n_quads : PF_LINES;
        int blocks = (work + threads - 1) / threads;   // flat, wide
        set_bits_kernel<<<blocks, threads>>>((const int4*)drop_idx, n_quads,
                                             drop_idx, k, (const char*)X);
    }

    // 2) fused copy + zero + mask clear (1024 float4s per 512-thread block)
    {
        int blocks = N_FLOAT4 / 1024;   // 8192
        apply_mask_kernel<<<blocks, 512>>>((const float4*)X, (float4*)out);
    }
}

// round 10
// speedup vs baseline: 1.4328x; 1.0169x over previous
#include <cuda_runtime.h>
#include <cstdint>

// Problem constants (fixed by the reference: SHAPE = (8192, 4096), P = 0.3)
#define N_ELEMS   (8192 * 4096)        // 33,554,432 floats
#define N_WORDS   (N_ELEMS / 32)       // 1,048,576 uint32 mask words = 4 MB
#define N_FLOAT4  (N_ELEMS / 4)        // 8,388,608 float4s

// How much of X to pull into L2 during the scatter phase (L2 ~126 MB total;
// leave room for the 4 MB mask + transient traffic).
#define PF_BYTES  (96 * 1024 * 1024)
#define PF_LINES  (PF_BYTES / 128)     // 786,432 cache lines

// Scratch: 1 bit per element. Zero at module load; apply re-zeroes it every
// pass for the next graph replay (self-cleaning).
__device__ uint32_t g_mask[N_WORDS];

// ---------------------------------------------------------------------------
// Kernel 1: scatter-set bits + forced L2 fill of X.
// Flat maximal-width launch: one int4 idx load + 4 RED.ORs per thread.
// Threads i < PF_LINES ALSO issue one real ld.global.cg.u32 per 128B line of
// X (asm volatile -> cannot be dropped like prefetch hints were in R8). The
// 4B load fills the full 128B line into L2 at evict-normal priority while
// DRAM is otherwise ~90% idle during this LSU-bound kernel.
// ---------------------------------------------------------------------------
__global__ void set_bits_kernel(const int4* __restrict__ idx4, int n_quads,
                                const int* __restrict__ idx, int k,
                                const char* __restrict__ Xbytes) {
    int i = blockIdx.x * blockDim.x + threadIdx.x;

    if (i < PF_LINES) {
        const char* p = Xbytes + (size_t)i * 128;
        unsigned int tmp;
        asm volatile("ld.global.cg.u32 %0, [%1];" : "=r"(tmp) : "l"(p)
                     : "memory");
    }

    if (i < n_quads) {
        int4 v = __ldcs(&idx4[i]);
        unsigned int a = (unsigned int)v.x;
        unsigned int b = (unsigned int)v.y;
        unsigned int c = (unsigned int)v.z;
        unsigned int d = (unsigned int)v.w;
        atomicOr(&g_mask[a >> 5], 1u << (a & 31));
        atomicOr(&g_mask[b >> 5], 1u << (b & 31));
        atomicOr(&g_mask[c >> 5], 1u << (c & 31));
        atomicOr(&g_mask[d >> 5], 1u << (d & 31));
    }
    // tail (k % 4 != 0)
    if (i == 0) {
        for (int j = n_quads * 4; j < k; j++) {
            unsigned int a = (unsigned int)idx[j];
            atomicOr(&g_mask[a >> 5], 1u << (a & 31));
        }
    }
}

// ---------------------------------------------------------------------------
// Kernel 2: fused copy + masked zero + mask self-clean (proven R4/R8 layout).
// Coalesced: consecutive threads -> consecutive float4s, ILP=2 block-strided.
// 8 adjacent same-warp threads share one mask word; the (tid&7)==0 lane
// cleans both of its group's words AFTER the loads (same warp -> program
// order makes the self-clean race-free).
// X read .ca default? No: __ldcg (L2-hit path, no L1 pollution of mask);
// out written .cs (evict-first, protects retained X lines).
// ---------------------------------------------------------------------------
__global__ void __launch_bounds__(512)
apply_mask_kernel(const float4* __restrict__ X, float4* __restrict__ out) {
    int tid = threadIdx.x;
    int i0 = blockIdx.x * 1024 + tid;      // first float4
    int i1 = i0 + 512;                     // second float4 (block-strided)

    uint32_t w0 = g_mask[i0 >> 3];
    uint32_t w1 = g_mask[i1 >> 3];
    float4 v0 = __ldcg(&X[i0]);
    float4 v1 = __ldcg(&X[i1]);

    uint32_t n0 = w0 >> ((i0 & 7) * 4);
    if (n0 & 1u) v0.x = 0.0f;
    if (n0 & 2u) v0.y = 0.0f;
    if (n0 & 4u) v0.z = 0.0f;
    if (n0 & 8u) v0.w = 0.0f;
    __stcs(&out[i0], v0);

    uint32_t n1 = w1 >> ((i1 & 7) * 4);
    if (n1 & 1u) v1.x = 0.0f;
    if (n1 & 2u) v1.y = 0.0f;
    if (n1 & 4u) v1.z = 0.0f;
    if (n1 & 8u) v1.w = 0.0f;
    __stcs(&out[i1], v1);

    // self-clean for next graph replay (one lane per 8-thread group)
    if ((tid & 7) == 0) {
        g_mask[i0 >> 3] = 0u;
        g_mask[i1 >> 3] = 0u;
    }
}

extern "C" void kernel_launch(void* const* d_in, const int* in_sizes, int n_in,
                              void* d_out, int out_size) {
    const float* X = (const float*)d_in[0];
    const int* drop_idx = (const int*)d_in[1];   // JAX x64-disabled => int32
    int k = in_sizes[1];                          // number of indices
    float* out = (float*)d_out;

    // 1) scatter bits + forced L2 fill of X (mask zero: init or prior apply)
    {
        int n_quads = k / 4;
        int threads = 256;
        int work = (n_quads > PF_LINES) ? n_quads : PF_LINES;
        int blocks = (work + threads - 1) / threads;   // flat, wide
        set_bits_kernel<<<blocks, threads>>>((const int4*)drop_idx, n_quads,
                                             drop_idx, k, (const char*)X);
    }

    // 2) fused copy + zero + mask clear (1024 float4s per 512-thread block)
    {
        int blocks = N_FLOAT4 / 1024;   // 8192
        apply_mask_kernel<<<blocks, 512>>>((const float4*)X, (float4*)out);
    }
}